// round 6
// baseline (speedup 1.0000x reference)
#include <cuda_runtime.h>
#include <cuda_fp16.h>
#include <mma.h>
#include <math.h>
#include <stdint.h>

using namespace nvcuda;

#define B_TOK 8192
#define H_DIM 1024
#define N_EXP 8
#define MAX_ROWS 17536   // 137 tiles * 128

// ---------------- scratch (static device memory; no allocations) ----------------
__device__ __half g_x_f16[B_TOK * H_DIM];
__device__ __half g_w_f16[N_EXP * H_DIM * H_DIM];   // [e][k][n] native layout

__device__ int   g_tok_e[B_TOK * 2];
__device__ float g_tok_w[B_TOK * 2];
__device__ int   g_counts[N_EXP];
__device__ int   g_cursor[N_EXP];
__device__ int   g_poff[N_EXP + 1];
__device__ int   g_tileoff[N_EXP + 1];
__device__ int   g_rows_tok[MAX_ROWS];
__device__ int   g_pos[B_TOK * 2];
__device__ __half g_ybuf_h[(size_t)MAX_ROWS * H_DIM];   // fp16 expert outputs

// ---------------- helpers ----------------
#define CP_ASYNC16(dst, src) \
    asm volatile("cp.async.cg.shared.global [%0], [%1], 16;\n" :: "r"(dst), "l"(src))
#define CP_COMMIT() asm volatile("cp.async.commit_group;\n" ::: "memory")
#define CP_WAIT(n)  asm volatile("cp.async.wait_group %0;\n" :: "n"(n) : "memory")

__device__ __forceinline__ uint32_t smem_u32(const void* p) {
    uint32_t a;
    asm("{ .reg .u64 t; cvta.to.shared.u64 t, %1; cvt.u32.u64 %0, t; }" : "=r"(a) : "l"(p));
    return a;
}
__device__ __forceinline__ uint32_t h2_u32(__half2 h) {
    return *reinterpret_cast<uint32_t*>(&h);
}

// ---------------- fused convert (fp32->fp16 x,w) + gate + init ----------------
// blocks [0,1024): gate (writes g_tok_e / g_tok_w ONLY — no count atomics here).
// blocks [1024,3072): convert + zero g_counts/g_cursor.
__global__ void convert_gate_kernel(const float* __restrict__ x,
                                    const float* __restrict__ w,
                                    const float* __restrict__ gw) {
    __shared__ float sgw[N_EXP * H_DIM];
    int tid = threadIdx.x;

    if (blockIdx.x < 1024) {
        // ---- gate ----
        for (int i = tid; i < N_EXP * H_DIM; i += blockDim.x) {
            int h = i >> 3, e = i & 7;
            sgw[e * H_DIM + h] = gw[i];
        }
        __syncthreads();
        int warp = tid >> 5, lane = tid & 31;
        int b = blockIdx.x * 8 + warp;
        const float* xr = x + (size_t)b * H_DIM;
        float acc[N_EXP];
#pragma unroll
        for (int e = 0; e < N_EXP; e++) acc[e] = 0.0f;
        for (int i = lane; i < H_DIM; i += 32) {
            float xv = xr[i];
#pragma unroll
            for (int e = 0; e < N_EXP; e++) acc[e] += xv * sgw[e * H_DIM + i];
        }
#pragma unroll
        for (int e = 0; e < N_EXP; e++) {
#pragma unroll
            for (int o = 16; o > 0; o >>= 1)
                acc[e] += __shfl_down_sync(0xffffffffu, acc[e], o);
        }
        if (lane == 0) {
            float b1v = -1e30f; int b1 = 0;
#pragma unroll
            for (int e = 0; e < N_EXP; e++)
                if (acc[e] > b1v) { b1v = acc[e]; b1 = e; }
            float b2v = -1e30f; int b2 = 0;
#pragma unroll
            for (int e = 0; e < N_EXP; e++)
                if (e != b1 && acc[e] > b2v) { b2v = acc[e]; b2 = e; }
            float e2 = expf(b2v - b1v);
            float inv = 1.0f / (1.0f + e2);
            g_tok_e[2 * b]     = b1;
            g_tok_e[2 * b + 1] = b2;
            g_tok_w[2 * b]     = inv;
            g_tok_w[2 * b + 1] = e2 * inv;
        }
        return;
    }

    // ---- convert + init ----
    int cb = blockIdx.x - 1024;                       // 0..2047
    int gid = cb * blockDim.x + tid;                  // 0..524287
    if (gid < N_EXP) { g_counts[gid] = 0; g_cursor[gid] = 0; }
    if (gid < MAX_ROWS) g_rows_tok[gid] = 0;

    const int n8 = (B_TOK * H_DIM) / 8;               // 1M iters of 8 floats
    const int stride = 2048 * blockDim.x;
    for (int j = gid; j < n8; j += stride) {
        const float4* xp = reinterpret_cast<const float4*>(x) + 2 * j;
        float4 v0 = xp[0], v1 = xp[1];
        uint4 hx;
        hx.x = h2_u32(__floats2half2_rn(v0.x, v0.y));
        hx.y = h2_u32(__floats2half2_rn(v0.z, v0.w));
        hx.z = h2_u32(__floats2half2_rn(v1.x, v1.y));
        hx.w = h2_u32(__floats2half2_rn(v1.z, v1.w));
        reinterpret_cast<uint4*>(g_x_f16)[j] = hx;

        const float4* wp = reinterpret_cast<const float4*>(w) + 2 * j;
        float4 u0 = wp[0], u1 = wp[1];
        uint4 hw;
        hw.x = h2_u32(__floats2half2_rn(u0.x, u0.y));
        hw.y = h2_u32(__floats2half2_rn(u0.z, u0.w));
        hw.z = h2_u32(__floats2half2_rn(u1.x, u1.y));
        hw.w = h2_u32(__floats2half2_rn(u1.z, u1.w));
        reinterpret_cast<uint4*>(g_w_f16)[j] = hw;
    }
}

// ---------------- count: rebuild per-expert counts from g_tok_e ----------------
__global__ void count_kernel() {
    __shared__ int s_cnt[N_EXP];
    int tid = threadIdx.x;
    if (tid < N_EXP) s_cnt[tid] = 0;
    __syncthreads();
    int b = blockIdx.x * blockDim.x + tid;
    if (b < B_TOK) {
        atomicAdd(&s_cnt[g_tok_e[2 * b]], 1);
        atomicAdd(&s_cnt[g_tok_e[2 * b + 1]], 1);
    }
    __syncthreads();
    if (tid < N_EXP) atomicAdd(&g_counts[tid], s_cnt[tid]);
}

// ---------------- place: prefix + scatter ----------------
__global__ void place_kernel() {
    __shared__ int s_poff[N_EXP + 1];
    if (threadIdx.x == 0) {
        int po = 0, to = 0;
        int poff[N_EXP + 1], tilo[N_EXP + 1];
        for (int e = 0; e < N_EXP; e++) {
            poff[e] = po; tilo[e] = to;
            int t = (g_counts[e] + 127) >> 7;
            to += t;
            po += t << 7;
        }
        poff[N_EXP] = po; tilo[N_EXP] = to;
        for (int e = 0; e <= N_EXP; e++) s_poff[e] = poff[e];
        if (blockIdx.x == 0) {
            for (int e = 0; e <= N_EXP; e++) { g_poff[e] = poff[e]; g_tileoff[e] = tilo[e]; }
        }
    }
    __syncthreads();
    int b = blockIdx.x * blockDim.x + threadIdx.x;
    if (b >= B_TOK) return;
#pragma unroll
    for (int j = 0; j < 2; j++) {
        int e = g_tok_e[2 * b + j];
        int p = s_poff[e] + atomicAdd(&g_cursor[e], 1);
        g_rows_tok[p] = b;
        g_pos[2 * b + j] = p;
    }
}

// ---------------- grouped GEMM: 128x128 tile, fp16 wmma, 3-stage cp.async ----------------
#define N_STAGE 3
#define SA_LD 72
#define SB_LD 136
#define SA_ST (128 * SA_LD)
#define SB_ST (64 * SB_LD)
#define SB_BASE (N_STAGE * SA_ST)
#define TOK_BASE_B ((N_STAGE * SA_ST + N_STAGE * SB_ST) * 2)
#define SMEM_TOTAL (TOK_BASE_B + 512)

__global__ __launch_bounds__(256, 2) void gemm_f16_kernel() {
    int mt = blockIdx.x;
    if (mt >= g_tileoff[N_EXP]) return;
    int e = 0;
    while (mt >= g_tileoff[e + 1]) e++;
    int row0 = g_poff[e] + ((mt - g_tileoff[e]) << 7);
    int n0 = blockIdx.y << 7;

    extern __shared__ char smem[];
    __half* sA = reinterpret_cast<__half*>(smem);
    __half* sB = reinterpret_cast<__half*>(smem) + SB_BASE;
    int* s_tok = reinterpret_cast<int*>(smem + TOK_BASE_B);
    uint32_t sbase = smem_u32(smem);

    int tid = threadIdx.x;
    if (tid < 128) s_tok[tid] = g_rows_tok[row0 + tid];
    __syncthreads();

    const __half* wbase = g_w_f16 + (size_t)e * H_DIM * H_DIM + n0;

    auto do_load = [&](int st, int k0) {
        uint32_t aoff = sbase + (uint32_t)(st * SA_ST * 2);
        uint32_t boff = sbase + (uint32_t)((SB_BASE + st * SB_ST) * 2);
#pragma unroll
        for (int ii = 0; ii < 4; ii++) {
            int idx = tid + ii * 256;
            int ra = idx >> 3, ca = idx & 7;
            const char* asrc = (const char*)(g_x_f16 + (size_t)s_tok[ra] * H_DIM + k0) + ca * 16;
            CP_ASYNC16(aoff + (uint32_t)(ra * SA_LD + ca * 8) * 2, asrc);
            int rb = idx >> 4, cb = idx & 15;
            const char* bsrc = (const char*)(wbase + (size_t)(k0 + rb) * H_DIM) + cb * 16;
            CP_ASYNC16(boff + (uint32_t)(rb * SB_LD + cb * 8) * 2, bsrc);
        }
        CP_COMMIT();
    };

    int wid = tid >> 5;
    int wm = wid & 3;
    int wn = wid >> 2;

    wmma::fragment<wmma::accumulator, 16, 16, 16, float> acc[2][4];
#pragma unroll
    for (int f = 0; f < 2; f++)
#pragma unroll
        for (int j = 0; j < 4; j++) wmma::fill_fragment(acc[f][j], 0.0f);

    do_load(0, 0);
    do_load(1, 64);

    for (int it = 0; it < 16; it++) {
        int st = it % N_STAGE;
        if (it == 15) { CP_WAIT(0); } else { CP_WAIT(1); }
        __syncthreads();
        if (it + 2 < 16) do_load((it + 2) % N_STAGE, (it + 2) << 6);

        const __half* A0 = sA + st * SA_ST + (wm * 32) * SA_LD;
        const __half* B0 = sB + st * SB_ST + wn * 64;
#pragma unroll
        for (int ks = 0; ks < 4; ks++) {
            wmma::fragment<wmma::matrix_a, 16, 16, 16, __half, wmma::row_major> af[2];
            wmma::load_matrix_sync(af[0], A0 + ks * 16, SA_LD);
            wmma::load_matrix_sync(af[1], A0 + 16 * SA_LD + ks * 16, SA_LD);
#pragma unroll
            for (int j = 0; j < 4; j++) {
                wmma::fragment<wmma::matrix_b, 16, 16, 16, __half, wmma::row_major> bf;
                wmma::load_matrix_sync(bf, B0 + (ks * 16) * SB_LD + j * 16, SB_LD);
                wmma::mma_sync(acc[0][j], af[0], bf, acc[0][j]);
                wmma::mma_sync(acc[1][j], af[1], bf, acc[1][j]);
            }
        }
    }

    // epilogue: f32 acc -> f16 fragment -> fp16 ybuf
    __half* yb = g_ybuf_h + (size_t)(row0 + wm * 32) * H_DIM + n0 + wn * 64;
#pragma unroll
    for (int f = 0; f < 2; f++)
#pragma unroll
        for (int j = 0; j < 4; j++) {
            wmma::fragment<wmma::accumulator, 16, 16, 16, __half> hacc;
#pragma unroll
            for (int t = 0; t < hacc.num_elements; t++)
                hacc.x[t] = __float2half(acc[f][j].x[t]);
            wmma::store_matrix_sync(yb + (size_t)(f * 16) * H_DIM + j * 16,
                                    hacc, H_DIM, wmma::mem_row_major);
        }
}

// ---------------- combine: out[b] = w0*y[p0] + w1*y[p1]  (8 elems/thread) ----------------
__global__ void combine_kernel(float* __restrict__ out) {
    int gid = blockIdx.x * blockDim.x + threadIdx.x;   // 1M threads
    int b = gid >> 7;
    int c8 = gid & 127;                                 // 8-half chunk index
    float w0 = g_tok_w[2 * b];
    float w1 = g_tok_w[2 * b + 1];
    int p0 = g_pos[2 * b];
    int p1 = g_pos[2 * b + 1];
    uint4 ya = reinterpret_cast<const uint4*>(g_ybuf_h + (size_t)p0 * H_DIM)[c8];
    uint4 yb = reinterpret_cast<const uint4*>(g_ybuf_h + (size_t)p1 * H_DIM)[c8];
    float4 o0, o1;
    float2 a, c;
    a = __half22float2(*reinterpret_cast<__half2*>(&ya.x));
    c = __half22float2(*reinterpret_cast<__half2*>(&yb.x));
    o0.x = w0 * a.x + w1 * c.x; o0.y = w0 * a.y + w1 * c.y;
    a = __half22float2(*reinterpret_cast<__half2*>(&ya.y));
    c = __half22float2(*reinterpret_cast<__half2*>(&yb.y));
    o0.z = w0 * a.x + w1 * c.x; o0.w = w0 * a.y + w1 * c.y;
    a = __half22float2(*reinterpret_cast<__half2*>(&ya.z));
    c = __half22float2(*reinterpret_cast<__half2*>(&yb.z));
    o1.x = w0 * a.x + w1 * c.x; o1.y = w0 * a.y + w1 * c.y;
    a = __half22float2(*reinterpret_cast<__half2*>(&ya.w));
    c = __half22float2(*reinterpret_cast<__half2*>(&yb.w));
    o1.z = w0 * a.x + w1 * c.x; o1.w = w0 * a.y + w1 * c.y;
    float4* op = reinterpret_cast<float4*>(out + (size_t)b * H_DIM + c8 * 8);
    op[0] = o0;
    op[1] = o1;
}

// ---------------- launch ----------------
extern "C" void kernel_launch(void* const* d_in, const int* in_sizes, int n_in,
                              void* d_out, int out_size) {
    const float* x  = (const float*)d_in[0];
    const float* gw = (const float*)d_in[1];
    const float* ew = (const float*)d_in[2];
    float* out = (float*)d_out;

    cudaFuncSetAttribute(gemm_f16_kernel, cudaFuncAttributeMaxDynamicSharedMemorySize, SMEM_TOTAL);

    convert_gate_kernel<<<3072, 256>>>(x, ew, gw);
    count_kernel<<<32, 256>>>();
    place_kernel<<<32, 256>>>();
    gemm_f16_kernel<<<dim3(137, 8), 256, SMEM_TOTAL>>>();
    combine_kernel<<<4096, 256>>>(out);
}

// round 7
// speedup vs baseline: 1.3727x; 1.3727x over previous
#include <cuda_runtime.h>
#include <cuda_fp16.h>
#include <mma.h>
#include <math.h>
#include <stdint.h>

using namespace nvcuda;

#define B_TOK 8192
#define H_DIM 1024
#define N_EXP 8
#define MAX_ROWS 17536   // 137 tiles * 128

// ---------------- scratch (static device memory; no allocations) ----------------
__device__ __half g_x_f16[B_TOK * H_DIM];
__device__ __half g_w_f16[N_EXP * H_DIM * H_DIM];   // [e][k][n] native layout

__device__ int   g_tok_e[B_TOK * 2];
__device__ float g_tok_w[B_TOK * 2];
__device__ int   g_counts[N_EXP];
__device__ int   g_cursor[N_EXP];
__device__ int   g_poff[N_EXP + 1];
__device__ int   g_tileoff[N_EXP + 1];
__device__ int   g_rows_tok[MAX_ROWS];
__device__ int   g_pos[B_TOK * 2];
__device__ __half g_ybuf_h[(size_t)MAX_ROWS * H_DIM];   // fp16 expert outputs

// ---------------- helpers ----------------
#define CP_ASYNC16(dst, src) \
    asm volatile("cp.async.cg.shared.global [%0], [%1], 16;\n" :: "r"(dst), "l"(src))
#define CP_COMMIT() asm volatile("cp.async.commit_group;\n" ::: "memory")
#define CP_WAIT(n)  asm volatile("cp.async.wait_group %0;\n" :: "n"(n) : "memory")

__device__ __forceinline__ uint32_t smem_u32(const void* p) {
    uint32_t a;
    asm("{ .reg .u64 t; cvta.to.shared.u64 t, %1; cvt.u32.u64 %0, t; }" : "=r"(a) : "l"(p));
    return a;
}
__device__ __forceinline__ uint32_t h2_u32(__half2 h) {
    return *reinterpret_cast<uint32_t*>(&h);
}

// ---------------- convert (fp32 -> fp16, x and w) + init fold (R4 exact) ----------------
__global__ void convert_kernel(const float* __restrict__ x, const float* __restrict__ w) {
    int gid = blockIdx.x * blockDim.x + threadIdx.x;
    if (gid < N_EXP) { g_counts[gid] = 0; g_cursor[gid] = 0; }
    if (gid < MAX_ROWS) g_rows_tok[gid] = 0;

    const int n4 = (B_TOK * H_DIM) / 4;
    const int stride = gridDim.x * blockDim.x;
    for (int j = gid; j < n4; j += stride) {
        float4 v = reinterpret_cast<const float4*>(x)[j];
        __half2 p0 = __floats2half2_rn(v.x, v.y);
        __half2 p1 = __floats2half2_rn(v.z, v.w);
        reinterpret_cast<__half2*>(g_x_f16)[2 * j]     = p0;
        reinterpret_cast<__half2*>(g_x_f16)[2 * j + 1] = p1;

        float4 u = reinterpret_cast<const float4*>(w)[j];
        p0 = __floats2half2_rn(u.x, u.y);
        p1 = __floats2half2_rn(u.z, u.w);
        reinterpret_cast<__half2*>(g_w_f16)[2 * j]     = p0;
        reinterpret_cast<__half2*>(g_w_f16)[2 * j + 1] = p1;
    }
}

// ---------------- gate (R4 exact) ----------------
__global__ void gate_kernel(const float* __restrict__ x, const float* __restrict__ gw) {
    __shared__ float sgw[N_EXP * H_DIM];
    int tid = threadIdx.x;
    for (int i = tid; i < N_EXP * H_DIM; i += blockDim.x) {
        int h = i >> 3, e = i & 7;
        sgw[e * H_DIM + h] = gw[i];
    }
    __syncthreads();
    int warp = tid >> 5, lane = tid & 31;
    int b = blockIdx.x * 8 + warp;
    const float* xr = x + (size_t)b * H_DIM;
    float acc[N_EXP];
#pragma unroll
    for (int e = 0; e < N_EXP; e++) acc[e] = 0.0f;
    for (int i = lane; i < H_DIM; i += 32) {
        float xv = xr[i];
#pragma unroll
        for (int e = 0; e < N_EXP; e++) acc[e] += xv * sgw[e * H_DIM + i];
    }
#pragma unroll
    for (int e = 0; e < N_EXP; e++) {
#pragma unroll
        for (int o = 16; o > 0; o >>= 1)
            acc[e] += __shfl_down_sync(0xffffffffu, acc[e], o);
    }
    if (lane == 0) {
        float b1v = -1e30f; int b1 = 0;
#pragma unroll
        for (int e = 0; e < N_EXP; e++)
            if (acc[e] > b1v) { b1v = acc[e]; b1 = e; }
        float b2v = -1e30f; int b2 = 0;
#pragma unroll
        for (int e = 0; e < N_EXP; e++)
            if (e != b1 && acc[e] > b2v) { b2v = acc[e]; b2 = e; }
        float e2 = expf(b2v - b1v);
        float inv = 1.0f / (1.0f + e2);
        g_tok_e[2 * b]     = b1;
        g_tok_e[2 * b + 1] = b2;
        g_tok_w[2 * b]     = inv;
        g_tok_w[2 * b + 1] = e2 * inv;
        atomicAdd(&g_counts[b1], 1);
        atomicAdd(&g_counts[b2], 1);
    }
}

// ---------------- scatter (R4 exact) ----------------
__global__ void scatter_kernel() {
    __shared__ int s_poff[N_EXP + 1];
    if (threadIdx.x == 0) {
        int po = 0, to = 0;
        int poff[N_EXP + 1], tilo[N_EXP + 1];
        for (int e = 0; e < N_EXP; e++) {
            poff[e] = po; tilo[e] = to;
            int t = (g_counts[e] + 127) >> 7;
            to += t;
            po += t << 7;
        }
        poff[N_EXP] = po; tilo[N_EXP] = to;
        for (int e = 0; e <= N_EXP; e++) s_poff[e] = poff[e];
        if (blockIdx.x == 0) {
            for (int e = 0; e <= N_EXP; e++) { g_poff[e] = poff[e]; g_tileoff[e] = tilo[e]; }
        }
    }
    __syncthreads();
    int b = blockIdx.x * blockDim.x + threadIdx.x;
    if (b >= B_TOK) return;
#pragma unroll
    for (int j = 0; j < 2; j++) {
        int e = g_tok_e[2 * b + j];
        int p = s_poff[e] + atomicAdd(&g_cursor[e], 1);
        g_rows_tok[p] = b;
        g_pos[2 * b + j] = p;
    }
}

// ---------------- grouped GEMM: R4 mainloop + smem-staged fp16 epilogue ----------------
#define N_STAGE 3
#define SA_LD 72
#define SB_LD 136
#define SA_ST (128 * SA_LD)
#define SB_ST (64 * SB_LD)
#define SB_BASE (N_STAGE * SA_ST)
#define TOK_BASE_B ((N_STAGE * SA_ST + N_STAGE * SB_ST) * 2)
#define SMEM_TOTAL (TOK_BASE_B + 512)
#define SF_LD 132   // f32 staging row pitch (floats)

__global__ __launch_bounds__(256, 2) void gemm_f16_kernel() {
    int mt = blockIdx.x;
    if (mt >= g_tileoff[N_EXP]) return;
    int e = 0;
    while (mt >= g_tileoff[e + 1]) e++;
    int row0 = g_poff[e] + ((mt - g_tileoff[e]) << 7);
    int n0 = blockIdx.y << 7;

    extern __shared__ char smem[];
    __half* sA = reinterpret_cast<__half*>(smem);
    __half* sB = reinterpret_cast<__half*>(smem) + SB_BASE;
    int* s_tok = reinterpret_cast<int*>(smem + TOK_BASE_B);
    uint32_t sbase = smem_u32(smem);

    int tid = threadIdx.x;
    if (tid < 128) s_tok[tid] = g_rows_tok[row0 + tid];
    __syncthreads();

    const __half* wbase = g_w_f16 + (size_t)e * H_DIM * H_DIM + n0;

    auto do_load = [&](int st, int k0) {
        uint32_t aoff = sbase + (uint32_t)(st * SA_ST * 2);
        uint32_t boff = sbase + (uint32_t)((SB_BASE + st * SB_ST) * 2);
#pragma unroll
        for (int ii = 0; ii < 4; ii++) {
            int idx = tid + ii * 256;
            int ra = idx >> 3, ca = idx & 7;
            const char* asrc = (const char*)(g_x_f16 + (size_t)s_tok[ra] * H_DIM + k0) + ca * 16;
            CP_ASYNC16(aoff + (uint32_t)(ra * SA_LD + ca * 8) * 2, asrc);
            int rb = idx >> 4, cb = idx & 15;
            const char* bsrc = (const char*)(wbase + (size_t)(k0 + rb) * H_DIM) + cb * 16;
            CP_ASYNC16(boff + (uint32_t)(rb * SB_LD + cb * 8) * 2, bsrc);
        }
        CP_COMMIT();
    };

    int wid = tid >> 5;
    int wm = wid & 3;
    int wn = wid >> 2;

    wmma::fragment<wmma::accumulator, 16, 16, 16, float> acc[2][4];
#pragma unroll
    for (int f = 0; f < 2; f++)
#pragma unroll
        for (int j = 0; j < 4; j++) wmma::fill_fragment(acc[f][j], 0.0f);

    do_load(0, 0);
    do_load(1, 64);

    for (int it = 0; it < 16; it++) {
        int st = it % N_STAGE;
        if (it == 15) { CP_WAIT(0); } else { CP_WAIT(1); }
        __syncthreads();
        if (it + 2 < 16) do_load((it + 2) % N_STAGE, (it + 2) << 6);

        const __half* A0 = sA + st * SA_ST + (wm * 32) * SA_LD;
        const __half* B0 = sB + st * SB_ST + wn * 64;
#pragma unroll
        for (int ks = 0; ks < 4; ks++) {
            wmma::fragment<wmma::matrix_a, 16, 16, 16, __half, wmma::row_major> af[2];
            wmma::load_matrix_sync(af[0], A0 + ks * 16, SA_LD);
            wmma::load_matrix_sync(af[1], A0 + 16 * SA_LD + ks * 16, SA_LD);
#pragma unroll
            for (int j = 0; j < 4; j++) {
                wmma::fragment<wmma::matrix_b, 16, 16, 16, __half, wmma::row_major> bf;
                wmma::load_matrix_sync(bf, B0 + (ks * 16) * SB_LD + j * 16, SB_LD);
                wmma::mma_sync(acc[0][j], af[0], bf, acc[0][j]);
                wmma::mma_sync(acc[1][j], af[1], bf, acc[1][j]);
            }
        }
    }

    // ---- epilogue: stage f32 accs into (now-dead) smem, then coalesced fp16 stores ----
    __syncthreads();   // all warps done reading smem stages
    float* sF = reinterpret_cast<float*>(smem);   // [128][SF_LD] = 67584 B < smem size
#pragma unroll
    for (int f = 0; f < 2; f++)
#pragma unroll
        for (int j = 0; j < 4; j++)
            wmma::store_matrix_sync(sF + (size_t)(wm * 32 + f * 16) * SF_LD + wn * 64 + j * 16,
                                    acc[f][j], SF_LD, wmma::mem_row_major);
    __syncthreads();
    // 128x128 f32 -> half2, 16 threads per row, 8 halves per thread
#pragma unroll
    for (int q = tid; q < 2048; q += 256) {
        int r = q >> 4;
        int c = (q & 15) << 3;
        const float* src = sF + (size_t)r * SF_LD + c;
        float4 f0 = *reinterpret_cast<const float4*>(src);
        float4 f1 = *reinterpret_cast<const float4*>(src + 4);
        uint4 h;
        h.x = h2_u32(__floats2half2_rn(f0.x, f0.y));
        h.y = h2_u32(__floats2half2_rn(f0.z, f0.w));
        h.z = h2_u32(__floats2half2_rn(f1.x, f1.y));
        h.w = h2_u32(__floats2half2_rn(f1.z, f1.w));
        *reinterpret_cast<uint4*>(g_ybuf_h + (size_t)(row0 + r) * H_DIM + n0 + c) = h;
    }
}

// ---------------- combine: out[b] = w0*y[p0] + w1*y[p1]  (fp16 reads, 8 elems/thread) ----------------
__global__ void combine_kernel(float* __restrict__ out) {
    int gid = blockIdx.x * blockDim.x + threadIdx.x;   // 1M threads
    int b = gid >> 7;
    int c8 = gid & 127;
    float w0 = g_tok_w[2 * b];
    float w1 = g_tok_w[2 * b + 1];
    int p0 = g_pos[2 * b];
    int p1 = g_pos[2 * b + 1];
    uint4 ya = reinterpret_cast<const uint4*>(g_ybuf_h + (size_t)p0 * H_DIM)[c8];
    uint4 yb = reinterpret_cast<const uint4*>(g_ybuf_h + (size_t)p1 * H_DIM)[c8];
    float4 o0, o1;
    float2 a, c;
    a = __half22float2(*reinterpret_cast<__half2*>(&ya.x));
    c = __half22float2(*reinterpret_cast<__half2*>(&yb.x));
    o0.x = w0 * a.x + w1 * c.x; o0.y = w0 * a.y + w1 * c.y;
    a = __half22float2(*reinterpret_cast<__half2*>(&ya.y));
    c = __half22float2(*reinterpret_cast<__half2*>(&yb.y));
    o0.z = w0 * a.x + w1 * c.x; o0.w = w0 * a.y + w1 * c.y;
    a = __half22float2(*reinterpret_cast<__half2*>(&ya.z));
    c = __half22float2(*reinterpret_cast<__half2*>(&yb.z));
    o1.x = w0 * a.x + w1 * c.x; o1.y = w0 * a.y + w1 * c.y;
    a = __half22float2(*reinterpret_cast<__half2*>(&ya.w));
    c = __half22float2(*reinterpret_cast<__half2*>(&yb.w));
    o1.z = w0 * a.x + w1 * c.x; o1.w = w0 * a.y + w1 * c.y;
    float4* op = reinterpret_cast<float4*>(out + (size_t)b * H_DIM + c8 * 8);
    op[0] = o0;
    op[1] = o1;
}

// ---------------- launch ----------------
extern "C" void kernel_launch(void* const* d_in, const int* in_sizes, int n_in,
                              void* d_out, int out_size) {
    const float* x  = (const float*)d_in[0];
    const float* gw = (const float*)d_in[1];
    const float* ew = (const float*)d_in[2];
    float* out = (float*)d_out;

    cudaFuncSetAttribute(gemm_f16_kernel, cudaFuncAttributeMaxDynamicSharedMemorySize, SMEM_TOTAL);

    convert_kernel<<<2048, 256>>>(x, ew);
    gate_kernel<<<1024, 256>>>(x, gw);
    scatter_kernel<<<32, 256>>>();
    gemm_f16_kernel<<<dim3(137, 8), 256, SMEM_TOTAL>>>();
    combine_kernel<<<4096, 256>>>(out);
}